// round 2
// baseline (speedup 1.0000x reference)
#include <cuda_runtime.h>
#include <cstdint>

#define NN    30000
#define RR    8
#define IND   256        // IN_DIM == HID == 256 (both layer input widths)
#define HIDD  256
#define ZDIM  128
#define NBASE 30
#define FW    (RR*IND + IND)   // 2304 fused feature width
#define NSEG  (NN*RR)
#define EE    480000

// ---- static scratch (no allocations allowed) ----
__device__ float g_feat[(size_t)NN * FW];   // 276 MB fused features (reused across layers)
__device__ float g_z[(size_t)NN * HIDD];    // layer-1 output
__device__ float g_W1[FW * HIDD];           // [W1_0..W1_7 ; root1] (2304 x 256)
__device__ float g_W2[FW * ZDIM];           // [W2_0..W2_7 ; root2] (2304 x 128)
__device__ float g_inv[NSEG];
__device__ int   g_cnt[NSEG];

// ---------------------------------------------------------------------------
// W build: W[r] = sum_b comp[r,b] * bases[b], stacked with root at the bottom.
// ---------------------------------------------------------------------------
__global__ void build_w_kernel(const float* __restrict__ bases,
                               const float* __restrict__ comp,
                               const float* __restrict__ root,
                               float* __restrict__ W, int in, int out)
{
    int idx = blockIdx.x * blockDim.x + threadIdx.x;
    int total = (RR * in + in) * out;
    if (idx >= total) return;
    int row = idx / out;
    int o = idx - row * out;
    if (row < RR * in) {
        int r = row / in;
        int i = row - r * in;
        float s = 0.f;
#pragma unroll
        for (int b = 0; b < NBASE; b++)
            s += comp[r * NBASE + b] * bases[((size_t)b * in + i) * out + o];
        W[idx] = s;
    } else {
        int i = row - RR * in;
        W[idx] = root[(size_t)i * out + o];
    }
}

// ---------------------------------------------------------------------------
// Segment counts -> reciprocals (topology-only, computed once)
// ---------------------------------------------------------------------------
__global__ void zero_cnt_kernel(int* __restrict__ cnt)
{
    int i = blockIdx.x * blockDim.x + threadIdx.x;
    if (i < NSEG) cnt[i] = 0;
}

__global__ void count_kernel(const int* __restrict__ dst,
                             const int* __restrict__ et,
                             int* __restrict__ cnt)
{
    int e = blockIdx.x * blockDim.x + threadIdx.x;
    if (e >= EE) return;
    atomicAdd(&cnt[dst[e] * RR + et[e]], 1);
}

__global__ void inv_kernel(const int* __restrict__ cnt, float* __restrict__ inv)
{
    int i = blockIdx.x * blockDim.x + threadIdx.x;
    if (i < NSEG) inv[i] = 1.0f / (float)max(cnt[i], 1);
}

// ---------------------------------------------------------------------------
// feat init: zero the 8 relation blocks, copy input row into the root block.
// One thread per float4 (576 float4 per row).
// ---------------------------------------------------------------------------
__global__ void init_feat_kernel(const float* __restrict__ x, float* __restrict__ feat)
{
    const int row4 = FW / 4;                // 576
    int idx = blockIdx.x * blockDim.x + threadIdx.x;
    int total = NN * row4;
    if (idx >= total) return;
    int row = idx / row4;
    int c4 = idx - row * row4;
    float4 v;
    if (c4 < (RR * IND) / 4)
        v = make_float4(0.f, 0.f, 0.f, 0.f);
    else
        v = ((const float4*)x)[(size_t)row * (IND / 4) + (c4 - (RR * IND) / 4)];
    ((float4*)feat)[(size_t)row * row4 + c4] = v;
}

// ---------------------------------------------------------------------------
// Edge scatter: one warp per edge, scaled by 1/cnt so means come out directly.
// Vectored L2 reductions (red.global.add.v4.f32, sm_90+).
// ---------------------------------------------------------------------------
__global__ void scatter_kernel(const float* __restrict__ x,
                               const int* __restrict__ src,
                               const int* __restrict__ dst,
                               const int* __restrict__ et,
                               const float* __restrict__ inv,
                               float* __restrict__ feat)
{
    int warp = (blockIdx.x * blockDim.x + threadIdx.x) >> 5;
    if (warp >= EE) return;
    int lane = threadIdx.x & 31;
    int s = src[warp];
    int d = dst[warp];
    int t = et[warp];
    float sc = inv[d * RR + t];
    const float4* xr = (const float4*)(x + (size_t)s * IND);
    float* base = feat + (size_t)d * FW + t * IND;
#pragma unroll
    for (int it = 0; it < 2; it++) {
        float4 v = xr[lane + it * 32];
        v.x *= sc; v.y *= sc; v.z *= sc; v.w *= sc;
        float* p = base + (lane + it * 32) * 4;
        asm volatile("red.global.add.v4.f32 [%0], {%1,%2,%3,%4};"
                     :: "l"(p), "f"(v.x), "f"(v.y), "f"(v.z), "f"(v.w)
                     : "memory");
    }
}

// ---------------------------------------------------------------------------
// fp32 tiled GEMM: C[M,N] = A[M,K] @ B[K,N] + bias, optional leaky-relu(0.01).
// 128x128 tile, BK=16, 256 threads, 8x8 microtile.
// ---------------------------------------------------------------------------
__global__ void __launch_bounds__(256)
gemm_kernel(const float* __restrict__ A, const float* __restrict__ Bm,
            const float* __restrict__ bias, float* __restrict__ C,
            int M, int K, int N, int leaky)
{
    __shared__ __align__(16) float As[16][128 + 4];
    __shared__ __align__(16) float Bs[16][128];

    const int bm = blockIdx.x * 128;
    const int bn = blockIdx.y * 128;
    const int tid = threadIdx.x;
    const int tx = tid & 15;
    const int ty = tid >> 4;

    float acc[8][8] = {};

    for (int k0 = 0; k0 < K; k0 += 16) {
#pragma unroll
        for (int i = 0; i < 2; i++) {
            int f = tid + i * 256;
            int r = f >> 2;            // row within 128-row tile
            int c = (f & 3) << 2;      // k-col (0,4,8,12)
            int gm = bm + r;
            float4 v = make_float4(0.f, 0.f, 0.f, 0.f);
            if (gm < M) v = *(const float4*)(A + (size_t)gm * K + k0 + c);
            As[c + 0][r] = v.x; As[c + 1][r] = v.y;
            As[c + 2][r] = v.z; As[c + 3][r] = v.w;
        }
#pragma unroll
        for (int i = 0; i < 2; i++) {
            int f = tid + i * 256;
            int r = f >> 5;            // k row 0..15
            int c = (f & 31) << 2;     // n col
            *(float4*)&Bs[r][c] = *(const float4*)(Bm + (size_t)(k0 + r) * N + bn + c);
        }
        __syncthreads();
#pragma unroll
        for (int kk = 0; kk < 16; kk++) {
            float4 a0 = *(const float4*)&As[kk][ty * 8];
            float4 a1 = *(const float4*)&As[kk][ty * 8 + 4];
            float4 b0 = *(const float4*)&Bs[kk][tx * 8];
            float4 b1 = *(const float4*)&Bs[kk][tx * 8 + 4];
            float a[8] = {a0.x, a0.y, a0.z, a0.w, a1.x, a1.y, a1.z, a1.w};
            float b[8] = {b0.x, b0.y, b0.z, b0.w, b1.x, b1.y, b1.z, b1.w};
#pragma unroll
            for (int i = 0; i < 8; i++)
#pragma unroll
                for (int j = 0; j < 8; j++)
                    acc[i][j] += a[i] * b[j];
        }
        __syncthreads();
    }

#pragma unroll
    for (int i = 0; i < 8; i++) {
        int gm = bm + ty * 8 + i;
        if (gm >= M) continue;
#pragma unroll
        for (int j = 0; j < 8; j += 4) {
            int gn = bn + tx * 8 + j;
            float4 v;
            v.x = acc[i][j + 0] + bias[gn + 0];
            v.y = acc[i][j + 1] + bias[gn + 1];
            v.z = acc[i][j + 2] + bias[gn + 2];
            v.w = acc[i][j + 3] + bias[gn + 3];
            if (leaky) {
                v.x = v.x > 0.f ? v.x : 0.01f * v.x;
                v.y = v.y > 0.f ? v.y : 0.01f * v.y;
                v.z = v.z > 0.f ? v.z : 0.01f * v.z;
                v.w = v.w > 0.f ? v.w : 0.01f * v.w;
            }
            *(float4*)(C + (size_t)gm * N + gn) = v;
        }
    }
}

// ---------------------------------------------------------------------------
extern "C" void kernel_launch(void* const* d_in, const int* in_sizes, int n_in,
                              void* d_out, int out_size)
{
    const float* x      = (const float*)d_in[0];
    const int*   ei     = (const int*)d_in[1];     // int32: JAX x64 disabled
    const int*   et     = (const int*)d_in[2];     // int32
    const float* bases1 = (const float*)d_in[3];
    const float* comp1  = (const float*)d_in[4];
    const float* root1  = (const float*)d_in[5];
    const float* bias1  = (const float*)d_in[6];
    const float* bases2 = (const float*)d_in[7];
    const float* comp2  = (const float*)d_in[8];
    const float* root2  = (const float*)d_in[9];
    const float* bias2  = (const float*)d_in[10];
    const int*   src    = ei;
    const int*   dst    = ei + EE;

    void *p;
    float *feat, *z, *W1, *W2, *inv; int* cnt;
    cudaGetSymbolAddress(&p, g_feat); feat = (float*)p;
    cudaGetSymbolAddress(&p, g_z);    z    = (float*)p;
    cudaGetSymbolAddress(&p, g_W1);   W1   = (float*)p;
    cudaGetSymbolAddress(&p, g_W2);   W2   = (float*)p;
    cudaGetSymbolAddress(&p, g_inv);  inv  = (float*)p;
    cudaGetSymbolAddress(&p, g_cnt);  cnt  = (int*)p;

    // Relation weight stacks
    {
        int tot = FW * HIDD;
        build_w_kernel<<<(tot + 255) / 256, 256>>>(bases1, comp1, root1, W1, IND, HIDD);
    }
    {
        int tot = FW * ZDIM;
        build_w_kernel<<<(tot + 255) / 256, 256>>>(bases2, comp2, root2, W2, HIDD, ZDIM);
    }

    // Segment reciprocals (topology only — shared by both layers)
    zero_cnt_kernel<<<(NSEG + 255) / 256, 256>>>(cnt);
    count_kernel<<<(EE + 255) / 256, 256>>>(dst, et, cnt);
    inv_kernel<<<(NSEG + 255) / 256, 256>>>(cnt, inv);

    const int initBlocks = (NN * (FW / 4) + 255) / 256;
    const int scatBlocks = (EE * 32 + 255) / 256;

    // ---- Layer 1 ----
    init_feat_kernel<<<initBlocks, 256>>>(x, feat);
    scatter_kernel<<<scatBlocks, 256>>>(x, src, dst, et, inv, feat);
    {
        dim3 g((NN + 127) / 128, HIDD / 128);
        gemm_kernel<<<g, 256>>>(feat, W1, bias1, z, NN, FW, HIDD, 1);
    }

    // ---- Layer 2 ----
    init_feat_kernel<<<initBlocks, 256>>>(z, feat);
    scatter_kernel<<<scatBlocks, 256>>>(z, src, dst, et, inv, feat);
    {
        dim3 g((NN + 127) / 128, ZDIM / 128);
        gemm_kernel<<<g, 256>>>(feat, W2, bias2, (float*)d_out, NN, FW, ZDIM, 0);
    }
}

// round 4
// speedup vs baseline: 2.3714x; 2.3714x over previous
#include <cuda_runtime.h>
#include <cstdint>

#define NN    30000
#define RR    8
#define KD    256          // input width of both layers (IN_DIM == HID == 256)
#define HIDD  256
#define ZDIM  128
#define NBASE 30
#define NSEG  (NN*RR)
#define EE    480000
#define NW1   (RR*HIDD + HIDD)   // 2304 : [Y_r blocks | root block]
#define NW2   (RR*ZDIM + ZDIM)   // 1152

// ---- static scratch (no allocations allowed) ----
__device__ float g_Y[(size_t)NN * NW1];     // transformed features (reused: layer2 needs less)
__device__ float g_z[(size_t)NN * HIDD];    // layer-1 aggregated output
__device__ float g_W1[KD * NW1];            // [256, 2304]
__device__ float g_W2[KD * NW2];            // [256, 1152]
__device__ float g_inv[NSEG];
__device__ int   g_cnt[NSEG];

// ---------------------------------------------------------------------------
// W build: Wcat[i][r*out+o] = sum_b comp[r,b]*bases[b,i,o];  Wcat[i][8*out+o]=root[i,o]
// ---------------------------------------------------------------------------
__global__ void build_w_kernel(const float* __restrict__ bases,
                               const float* __restrict__ comp,
                               const float* __restrict__ root,
                               float* __restrict__ W, int out)
{
    int idx = blockIdx.x * blockDim.x + threadIdx.x;
    int ncol = (RR + 1) * out;
    int total = KD * ncol;
    if (idx >= total) return;
    int i = idx / ncol;
    int col = idx - i * ncol;
    int r = col / out;
    int o = col - r * out;
    if (r < RR) {
        float s = 0.f;
#pragma unroll
        for (int b = 0; b < NBASE; b++)
            s += comp[r * NBASE + b] * bases[((size_t)b * KD + i) * out + o];
        W[idx] = s;
    } else {
        W[idx] = root[(size_t)i * out + o];
    }
}

// ---------------------------------------------------------------------------
// Segment counts -> reciprocals (topology-only)
// ---------------------------------------------------------------------------
__global__ void zero_cnt_kernel(int* __restrict__ cnt)
{
    int i = blockIdx.x * blockDim.x + threadIdx.x;
    if (i < NSEG) cnt[i] = 0;
}

__global__ void count_kernel(const int* __restrict__ dst,
                             const int* __restrict__ et,
                             int* __restrict__ cnt)
{
    int e = blockIdx.x * blockDim.x + threadIdx.x;
    if (e >= EE) return;
    atomicAdd(&cnt[dst[e] * RR + et[e]], 1);
}

__global__ void inv_kernel(const int* __restrict__ cnt, float* __restrict__ inv)
{
    int i = blockIdx.x * blockDim.x + threadIdx.x;
    if (i < NSEG) inv[i] = 1.0f / (float)max(cnt[i], 1);
}

// ---------------------------------------------------------------------------
// tf32 tensor-core GEMM: Y[M,N] = A[M,256] @ W[256,N]   (no epilogue)
// 128x128 tile, BK=32, 256 threads = 8 warps (4x2), warp tile 32x64,
// mma.sync.m16n8k8.tf32.
// ---------------------------------------------------------------------------
__device__ __forceinline__ unsigned f2tf32(float f)
{
    unsigned u;
    asm("cvt.rna.tf32.f32 %0, %1;" : "=r"(u) : "f"(f));
    return u;
}

__device__ __forceinline__ void mma_tf32(float c[4], const unsigned a[4], const unsigned b[2])
{
    asm volatile("mma.sync.aligned.m16n8k8.row.col.f32.tf32.tf32.f32 "
                 "{%0,%1,%2,%3}, {%4,%5,%6,%7}, {%8,%9}, {%0,%1,%2,%3};"
                 : "+f"(c[0]), "+f"(c[1]), "+f"(c[2]), "+f"(c[3])
                 : "r"(a[0]), "r"(a[1]), "r"(a[2]), "r"(a[3]),
                   "r"(b[0]), "r"(b[1]));
}

__global__ void __launch_bounds__(256)
gemm_tf32_kernel(const float* __restrict__ A, const float* __restrict__ W,
                 float* __restrict__ Y, int M, int N)
{
    __shared__ unsigned As[32][136];   // k-major: As[k][m], stride 136 -> conflict-free frags
    __shared__ unsigned Bs[32][136];   // Bs[k][n]

    const int tid   = threadIdx.x;
    const int lane  = tid & 31;
    const int warp  = tid >> 5;
    const int warpM = warp >> 1;       // 0..3
    const int warpN = warp & 1;        // 0..1
    const int gid   = lane >> 2;       // 0..7
    const int tig   = lane & 3;        // 0..3
    const int bm    = blockIdx.x * 128;
    const int bn    = blockIdx.y * 128;

    float acc[2][8][4];
#pragma unroll
    for (int mt = 0; mt < 2; mt++)
#pragma unroll
        for (int nt = 0; nt < 8; nt++)
#pragma unroll
            for (int q = 0; q < 4; q++) acc[mt][nt][q] = 0.f;

    for (int k0 = 0; k0 < KD; k0 += 32) {
        // --- A tile: 128 rows x 32 k, transpose into As[k][m], cvt to tf32 ---
        {
            int m  = tid & 127;
            int fb = tid >> 7;          // 0 or 1
            int gm = bm + m;
#pragma unroll
            for (int j = 0; j < 4; j++) {
                int f = fb + 2 * j;     // float4 index 0..7 within the 32-k row
                float4 v = make_float4(0.f, 0.f, 0.f, 0.f);
                if (gm < M) v = *(const float4*)(A + (size_t)gm * KD + k0 + f * 4);
                As[f * 4 + 0][m] = f2tf32(v.x);
                As[f * 4 + 1][m] = f2tf32(v.y);
                As[f * 4 + 2][m] = f2tf32(v.z);
                As[f * 4 + 3][m] = f2tf32(v.w);
            }
        }
        // --- B tile: 32 k x 128 n, row-major into Bs[k][n] ---
        {
            int k  = tid >> 3;          // 0..31
            int fq = tid & 7;
#pragma unroll
            for (int j = 0; j < 4; j++) {
                int f4 = fq + 8 * j;    // 0..31 float4 within row
                float4 v = *(const float4*)(W + (size_t)(k0 + k) * N + bn + f4 * 4);
                uint4 u;
                u.x = f2tf32(v.x); u.y = f2tf32(v.y);
                u.z = f2tf32(v.z); u.w = f2tf32(v.w);
                *(uint4*)&Bs[k][f4 * 4] = u;
            }
        }
        __syncthreads();

#pragma unroll
        for (int ks = 0; ks < 4; ks++) {
            const int kb = ks * 8;
            unsigned af[2][4];
#pragma unroll
            for (int mt = 0; mt < 2; mt++) {
                int mrow = warpM * 32 + mt * 16;
                af[mt][0] = As[kb + tig][mrow + gid];
                af[mt][1] = As[kb + tig][mrow + gid + 8];
                af[mt][2] = As[kb + tig + 4][mrow + gid];
                af[mt][3] = As[kb + tig + 4][mrow + gid + 8];
            }
#pragma unroll
            for (int nt = 0; nt < 8; nt++) {
                int ncol = warpN * 64 + nt * 8;
                unsigned bf[2];
                bf[0] = Bs[kb + tig][ncol + gid];
                bf[1] = Bs[kb + tig + 4][ncol + gid];
                mma_tf32(acc[0][nt], af[0], bf);
                mma_tf32(acc[1][nt], af[1], bf);
            }
        }
        __syncthreads();
    }

    // --- epilogue: plain store ---
#pragma unroll
    for (int mt = 0; mt < 2; mt++) {
#pragma unroll
        for (int nt = 0; nt < 8; nt++) {
            int r0 = bm + warpM * 32 + mt * 16 + gid;
            int c  = bn + warpN * 64 + nt * 8 + tig * 2;
            if (r0 < M) {
                float2 v0 = make_float2(acc[mt][nt][0], acc[mt][nt][1]);
                *(float2*)(Y + (size_t)r0 * N + c) = v0;
            }
            int r1 = r0 + 8;
            if (r1 < M) {
                float2 v1 = make_float2(acc[mt][nt][2], acc[mt][nt][3]);
                *(float2*)(Y + (size_t)r1 * N + c) = v1;
            }
        }
    }
}

// ---------------------------------------------------------------------------
// init: out[n][o] = Y[n][OFF+o] + bias[o]
// ---------------------------------------------------------------------------
template<int YS, int WID, int OFF>
__global__ void init_out_kernel(const float* __restrict__ Y,
                                const float* __restrict__ bias,
                                float* __restrict__ out)
{
    int idx = blockIdx.x * blockDim.x + threadIdx.x;
    int total = NN * (WID / 4);
    if (idx >= total) return;
    int n  = idx / (WID / 4);
    int c4 = idx - n * (WID / 4);
    float4 v = *(const float4*)(Y + (size_t)n * YS + OFF + c4 * 4);
    float4 b = *(const float4*)(bias + c4 * 4);
    v.x += b.x; v.y += b.y; v.z += b.z; v.w += b.w;
    *(float4*)(out + (size_t)n * WID + c4 * 4) = v;
}

// ---------------------------------------------------------------------------
// Scatter of transformed features: out[dst] += inv * Y[src, rel-block]
// One warp per edge; vectored L2 reductions. Destination is small (L2-resident).
// ---------------------------------------------------------------------------
template<int YS, int WID>
__global__ void scatter_kernel(const float* __restrict__ Y,
                               const int* __restrict__ src,
                               const int* __restrict__ dst,
                               const int* __restrict__ et,
                               const float* __restrict__ inv,
                               float* __restrict__ out)
{
    int warp = (blockIdx.x * blockDim.x + threadIdx.x) >> 5;
    if (warp >= EE) return;
    int lane = threadIdx.x & 31;
    int s = src[warp];
    int d = dst[warp];
    int t = et[warp];
    float sc = inv[d * RR + t];
    const float4* yr = (const float4*)(Y + (size_t)s * YS + t * WID);
    float* base = out + (size_t)d * WID;
#pragma unroll
    for (int it = 0; it < WID / 128; it++) {
        float4 v = yr[lane + it * 32];
        v.x *= sc; v.y *= sc; v.z *= sc; v.w *= sc;
        float* p = base + (lane + it * 32) * 4;
        asm volatile("red.global.add.v4.f32 [%0], {%1,%2,%3,%4};"
                     :: "l"(p), "f"(v.x), "f"(v.y), "f"(v.z), "f"(v.w)
                     : "memory");
    }
}

// ---------------------------------------------------------------------------
__global__ void leaky_kernel(float* __restrict__ z)
{
    int idx = blockIdx.x * blockDim.x + threadIdx.x;
    int total = NN * HIDD / 4;
    if (idx >= total) return;
    float4 v = ((float4*)z)[idx];
    v.x = v.x > 0.f ? v.x : 0.01f * v.x;
    v.y = v.y > 0.f ? v.y : 0.01f * v.y;
    v.z = v.z > 0.f ? v.z : 0.01f * v.z;
    v.w = v.w > 0.f ? v.w : 0.01f * v.w;
    ((float4*)z)[idx] = v;
}

// ---------------------------------------------------------------------------
extern "C" void kernel_launch(void* const* d_in, const int* in_sizes, int n_in,
                              void* d_out, int out_size)
{
    const float* x      = (const float*)d_in[0];
    const int*   ei     = (const int*)d_in[1];     // int32 (JAX x64 disabled)
    const int*   et     = (const int*)d_in[2];
    const float* bases1 = (const float*)d_in[3];
    const float* comp1  = (const float*)d_in[4];
    const float* root1  = (const float*)d_in[5];
    const float* bias1  = (const float*)d_in[6];
    const float* bases2 = (const float*)d_in[7];
    const float* comp2  = (const float*)d_in[8];
    const float* root2  = (const float*)d_in[9];
    const float* bias2  = (const float*)d_in[10];
    const int*   src    = ei;
    const int*   dst    = ei + EE;

    void *p;
    float *Y, *z, *W1, *W2, *inv; int* cnt;
    cudaGetSymbolAddress(&p, g_Y);   Y   = (float*)p;
    cudaGetSymbolAddress(&p, g_z);   z   = (float*)p;
    cudaGetSymbolAddress(&p, g_W1);  W1  = (float*)p;
    cudaGetSymbolAddress(&p, g_W2);  W2  = (float*)p;
    cudaGetSymbolAddress(&p, g_inv); inv = (float*)p;
    cudaGetSymbolAddress(&p, g_cnt); cnt = (int*)p;

    // Relation weight stacks
    build_w_kernel<<<(KD * NW1 + 255) / 256, 256>>>(bases1, comp1, root1, W1, HIDD);
    build_w_kernel<<<(KD * NW2 + 255) / 256, 256>>>(bases2, comp2, root2, W2, ZDIM);

    // Segment reciprocals
    zero_cnt_kernel<<<(NSEG + 255) / 256, 256>>>(cnt);
    count_kernel<<<(EE + 255) / 256, 256>>>(dst, et, cnt);
    inv_kernel<<<(NSEG + 255) / 256, 256>>>(cnt, inv);

    const int scatBlocks = (EE * 32 + 255) / 256;

    // ---- Layer 1 ----
    {
        dim3 g((NN + 127) / 128, NW1 / 128);
        gemm_tf32_kernel<<<g, 256>>>(x, W1, Y, NN, NW1);
    }
    init_out_kernel<NW1, HIDD, RR * HIDD><<<(NN * HIDD / 4 + 255) / 256, 256>>>(Y, bias1, z);
    scatter_kernel<NW1, HIDD><<<scatBlocks, 256>>>(Y, src, dst, et, inv, z);
    leaky_kernel<<<(NN * HIDD / 4 + 255) / 256, 256>>>(z);

    // ---- Layer 2 ----
    {
        dim3 g((NN + 127) / 128, NW2 / 128);
        gemm_tf32_kernel<<<g, 256>>>(z, W2, Y, NN, NW2);
    }
    init_out_kernel<NW2, ZDIM, RR * ZDIM><<<(NN * ZDIM / 4 + 255) / 256, 256>>>(Y, bias2, (float*)d_out);
    scatter_kernel<NW2, ZDIM><<<scatBlocks, 256>>>(Y, src, dst, et, inv, (float*)d_out);
}

// round 5
// speedup vs baseline: 3.0454x; 1.2842x over previous
#include <cuda_runtime.h>
#include <cstdint>

#define NN    30000
#define RR    8
#define KD    256
#define HIDD  256
#define ZDIM  128
#define NBASE 30
#define NSEG  (NN*RR)
#define EE    480000
#define NW1   (RR*HIDD + HIDD)   // 2304
#define NW2   (RR*ZDIM + ZDIM)   // 1152
#define NR1   (RR*HIDD)          // 2048
#define NR2   (RR*ZDIM)          // 1024

// ---- static scratch ----
__device__ float g_Y[(size_t)NN * NR1];     // relation-block outputs (layer2 reuses)
__device__ float g_z[(size_t)NN * HIDD];
__device__ float g_xr[(size_t)NN * KD];     // tf32-rounded x
__device__ float g_W1[KD * NW1];
__device__ float g_W2[KD * NW2];
__device__ float g_inv[NSEG];
__device__ int   g_cnt[NSEG];
__device__ int   g_hist[NN];
__device__ int   g_off[NN];
__device__ int   g_es[EE];
__device__ int   g_ed[EE];
__device__ int   g_et[EE];
__device__ float g_esc[EE];

__device__ __forceinline__ unsigned f2tf32(float f)
{
    unsigned u;
    asm("cvt.rna.tf32.f32 %0, %1;" : "=r"(u) : "f"(f));
    return u;
}
__device__ __forceinline__ float rtf32(float f) { return __uint_as_float(f2tf32(f)); }

// ---------------------------------------------------------------------------
// W build with tf32 rounding baked in
// ---------------------------------------------------------------------------
__global__ void build_w_kernel(const float* __restrict__ bases,
                               const float* __restrict__ comp,
                               const float* __restrict__ root,
                               float* __restrict__ W, int out)
{
    int idx = blockIdx.x * blockDim.x + threadIdx.x;
    int ncol = (RR + 1) * out;
    int total = KD * ncol;
    if (idx >= total) return;
    int i = idx / ncol;
    int col = idx - i * ncol;
    int r = col / out;
    int o = col - r * out;
    float s;
    if (r < RR) {
        s = 0.f;
#pragma unroll
        for (int b = 0; b < NBASE; b++)
            s += comp[r * NBASE + b] * bases[((size_t)b * KD + i) * out + o];
    } else {
        s = root[(size_t)i * out + o];
    }
    W[idx] = rtf32(s);
}

__global__ void round_x_kernel(const float* __restrict__ x, float* __restrict__ xr)
{
    int idx = blockIdx.x * blockDim.x + threadIdx.x;
    if (idx >= NN * KD / 4) return;
    float4 v = ((const float4*)x)[idx];
    v.x = rtf32(v.x); v.y = rtf32(v.y); v.z = rtf32(v.z); v.w = rtf32(v.w);
    ((float4*)xr)[idx] = v;
}

// ---------------------------------------------------------------------------
// Topology prep: counts per (dst,rel), hist per src
// ---------------------------------------------------------------------------
__global__ void zero_topo_kernel(int* __restrict__ cnt, int* __restrict__ hist)
{
    int i = blockIdx.x * blockDim.x + threadIdx.x;
    if (i < NSEG) cnt[i] = 0;
    if (i < NN) hist[i] = 0;
}

__global__ void count_kernel(const int* __restrict__ src,
                             const int* __restrict__ dst,
                             const int* __restrict__ et,
                             int* __restrict__ cnt, int* __restrict__ hist)
{
    int e = blockIdx.x * blockDim.x + threadIdx.x;
    if (e >= EE) return;
    atomicAdd(&cnt[dst[e] * RR + et[e]], 1);
    atomicAdd(&hist[src[e]], 1);
}

__global__ void inv_kernel(const int* __restrict__ cnt, float* __restrict__ inv)
{
    int i = blockIdx.x * blockDim.x + threadIdx.x;
    if (i < NSEG) inv[i] = 1.0f / (float)max(cnt[i], 1);
}

// Single-block exclusive scan of hist[NN] -> off[NN]  (1024 threads, 32 bins each)
__global__ void __launch_bounds__(1024) scan_kernel(const int* __restrict__ hist,
                                                    int* __restrict__ off)
{
    __shared__ int part[1024];
    int tid = threadIdx.x;
    int base = tid * 32;
    int s = 0;
#pragma unroll
    for (int j = 0; j < 32; j++) {
        int idx = base + j;
        if (idx < NN) s += hist[idx];
    }
    part[tid] = s;
    __syncthreads();
    for (int d = 1; d < 1024; d <<= 1) {
        int v = 0;
        if (tid >= d) v = part[tid - d];
        __syncthreads();
        if (tid >= d) part[tid] += v;
        __syncthreads();
    }
    int run = (tid > 0) ? part[tid - 1] : 0;
#pragma unroll
    for (int j = 0; j < 32; j++) {
        int idx = base + j;
        if (idx < NN) { off[idx] = run; run += hist[idx]; }
    }
}

__global__ void permute_kernel(const int* __restrict__ src,
                               const int* __restrict__ dst,
                               const int* __restrict__ et,
                               const float* __restrict__ inv,
                               int* __restrict__ off,
                               int* __restrict__ es, int* __restrict__ ed,
                               int* __restrict__ ets, float* __restrict__ esc)
{
    int e = blockIdx.x * blockDim.x + threadIdx.x;
    if (e >= EE) return;
    int s = src[e], d = dst[e], t = et[e];
    int pos = atomicAdd(&off[s], 1);
    es[pos] = s; ed[pos] = d; ets[pos] = t;
    esc[pos] = inv[d * RR + t];
}

// ---------------------------------------------------------------------------
// tf32 GEMM, cp.async double-buffered, split epilogue:
//   cols <  NR : Yr[row*NR + c]
//   cols >= NR : dest[row*OUT + c-NR] + bias
// Block 128x128, BK=32, 256 threads, warp tile 32x64, m16n8k8 tf32.
// Dynamic smem: As 2x128x36, Bs 2x32x136 floats = 71680 B.
// ---------------------------------------------------------------------------
#define AS_STRIDE 36
#define BS_STRIDE 136
#define AS_WORDS  (128*AS_STRIDE)      // 4608
#define BS_WORDS  (32*BS_STRIDE)       // 4352
#define SMEM_BYTES ((2*AS_WORDS + 2*BS_WORDS)*4)

__device__ __forceinline__ void cp16(uint32_t saddr, const void* g, bool pred)
{
    int sz = pred ? 16 : 0;
    asm volatile("cp.async.cg.shared.global [%0], [%1], 16, %2;"
                 :: "r"(saddr), "l"(g), "r"(sz));
}

__device__ __forceinline__ void mma_tf32(float c[4], const unsigned a[4], const unsigned b[2])
{
    asm volatile("mma.sync.aligned.m16n8k8.row.col.f32.tf32.tf32.f32 "
                 "{%0,%1,%2,%3}, {%4,%5,%6,%7}, {%8,%9}, {%0,%1,%2,%3};"
                 : "+f"(c[0]), "+f"(c[1]), "+f"(c[2]), "+f"(c[3])
                 : "r"(a[0]), "r"(a[1]), "r"(a[2]), "r"(a[3]),
                   "r"(b[0]), "r"(b[1]));
}

__global__ void __launch_bounds__(256)
gemm2_kernel(const float* __restrict__ A, const float* __restrict__ W,
             float* __restrict__ Yr, float* __restrict__ dest,
             const float* __restrict__ bias,
             int M, int Ntot, int NR, int OUT)
{
    extern __shared__ float sm[];
    const uint32_t smb = (uint32_t)__cvta_generic_to_shared(sm);

    const int tid   = threadIdx.x;
    const int lane  = tid & 31;
    const int warp  = tid >> 5;
    const int warpM = warp >> 1;
    const int warpN = warp & 1;
    const int gid   = lane >> 2;
    const int tig   = lane & 3;
    const int bm    = blockIdx.x * 128;
    const int bn    = blockIdx.y * 128;

    float acc[2][8][4];
#pragma unroll
    for (int mt = 0; mt < 2; mt++)
#pragma unroll
        for (int nt = 0; nt < 8; nt++)
#pragma unroll
            for (int q = 0; q < 4; q++) acc[mt][nt][q] = 0.f;

    auto loadA = [&](int stage, int k0) {
        uint32_t base = smb + (uint32_t)(stage * AS_WORDS) * 4;
#pragma unroll
        for (int i = 0; i < 4; i++) {
            int c = tid + 256 * i;
            int row = c >> 3, kc = c & 7;
            int gm = bm + row;
            const float* g = A + (size_t)gm * KD + k0 + kc * 4;
            cp16(base + (uint32_t)(row * AS_STRIDE + kc * 4) * 4, g, gm < M);
        }
    };
    auto loadB = [&](int stage, int k0) {
        uint32_t base = smb + (uint32_t)(2 * AS_WORDS + stage * BS_WORDS) * 4;
#pragma unroll
        for (int i = 0; i < 4; i++) {
            int c = tid + 256 * i;
            int kr = c >> 5, nc = c & 31;
            const float* g = W + (size_t)(k0 + kr) * Ntot + bn + nc * 4;
            cp16(base + (uint32_t)(kr * BS_STRIDE + nc * 4) * 4, g, true);
        }
    };

    loadA(0, 0); loadB(0, 0);
    asm volatile("cp.async.commit_group;");

    const int KT = KD / 32;     // 8
    for (int kt = 0; kt < KT; kt++) {
        int cur = kt & 1;
        if (kt + 1 < KT) {
            loadA(cur ^ 1, (kt + 1) * 32);
            loadB(cur ^ 1, (kt + 1) * 32);
            asm volatile("cp.async.commit_group;");
            asm volatile("cp.async.wait_group 1;");
        } else {
            asm volatile("cp.async.wait_group 0;");
        }
        __syncthreads();

        const float* As = sm + cur * AS_WORDS;
        const float* Bs = sm + 2 * AS_WORDS + cur * BS_WORDS;
        const unsigned* Au = (const unsigned*)As;
        const unsigned* Bu = (const unsigned*)Bs;

#pragma unroll
        for (int ks = 0; ks < 4; ks++) {
            const int kb = ks * 8;
            unsigned af[2][4];
#pragma unroll
            for (int mt = 0; mt < 2; mt++) {
                int mrow = warpM * 32 + mt * 16;
                af[mt][0] = Au[(mrow + gid) * AS_STRIDE + kb + tig];
                af[mt][1] = Au[(mrow + gid + 8) * AS_STRIDE + kb + tig];
                af[mt][2] = Au[(mrow + gid) * AS_STRIDE + kb + tig + 4];
                af[mt][3] = Au[(mrow + gid + 8) * AS_STRIDE + kb + tig + 4];
            }
#pragma unroll
            for (int nt = 0; nt < 8; nt++) {
                int ncol = warpN * 64 + nt * 8;
                unsigned bf[2];
                bf[0] = Bu[(kb + tig) * BS_STRIDE + ncol + gid];
                bf[1] = Bu[(kb + tig + 4) * BS_STRIDE + ncol + gid];
                mma_tf32(acc[0][nt], af[0], bf);
                mma_tf32(acc[1][nt], af[1], bf);
            }
        }
        __syncthreads();
    }

    // split epilogue
#pragma unroll
    for (int mt = 0; mt < 2; mt++) {
#pragma unroll
        for (int nt = 0; nt < 8; nt++) {
            int r0 = bm + warpM * 32 + mt * 16 + gid;
            int r1 = r0 + 8;
            int c  = bn + warpN * 64 + nt * 8 + tig * 2;
            if (c < NR) {
                if (r0 < M) *(float2*)(Yr + (size_t)r0 * NR + c) =
                    make_float2(acc[mt][nt][0], acc[mt][nt][1]);
                if (r1 < M) *(float2*)(Yr + (size_t)r1 * NR + c) =
                    make_float2(acc[mt][nt][2], acc[mt][nt][3]);
            } else {
                int cc = c - NR;
                float bx = bias[cc], by = bias[cc + 1];
                if (r0 < M) *(float2*)(dest + (size_t)r0 * OUT + cc) =
                    make_float2(acc[mt][nt][0] + bx, acc[mt][nt][1] + by);
                if (r1 < M) *(float2*)(dest + (size_t)r1 * OUT + cc) =
                    make_float2(acc[mt][nt][2] + bx, acc[mt][nt][3] + by);
            }
        }
    }
}

// ---------------------------------------------------------------------------
// Scatter (src-sorted): out[dst] += esc * Yr[src, rel-block]
// ---------------------------------------------------------------------------
template<int OUT>
__global__ void scatter_kernel(const float* __restrict__ Yr,
                               const int* __restrict__ es,
                               const int* __restrict__ ed,
                               const int* __restrict__ ets,
                               const float* __restrict__ esc,
                               float* __restrict__ out)
{
    const int NR = RR * OUT;
    int w = (blockIdx.x * blockDim.x + threadIdx.x) >> 5;
    if (w >= EE) return;
    int lane = threadIdx.x & 31;
    int s = es[w], d = ed[w], t = ets[w];
    float sc = esc[w];
    const float4* yr = (const float4*)(Yr + (size_t)s * NR + t * OUT);
    float* base = out + (size_t)d * OUT;
#pragma unroll
    for (int it = 0; it < OUT / 128; it++) {
        float4 v = yr[lane + it * 32];
        v.x *= sc; v.y *= sc; v.z *= sc; v.w *= sc;
        float* p = base + (lane + it * 32) * 4;
        asm volatile("red.global.add.v4.f32 [%0], {%1,%2,%3,%4};"
                     :: "l"(p), "f"(v.x), "f"(v.y), "f"(v.z), "f"(v.w)
                     : "memory");
    }
}

// ---------------------------------------------------------------------------
// leaky relu + tf32 rounding (z feeds GEMM2 as A operand)
// ---------------------------------------------------------------------------
__global__ void leaky_kernel(float* __restrict__ z)
{
    int idx = blockIdx.x * blockDim.x + threadIdx.x;
    if (idx >= NN * HIDD / 4) return;
    float4 v = ((float4*)z)[idx];
    v.x = rtf32(v.x > 0.f ? v.x : 0.01f * v.x);
    v.y = rtf32(v.y > 0.f ? v.y : 0.01f * v.y);
    v.z = rtf32(v.z > 0.f ? v.z : 0.01f * v.z);
    v.w = rtf32(v.w > 0.f ? v.w : 0.01f * v.w);
    ((float4*)z)[idx] = v;
}

// ---------------------------------------------------------------------------
extern "C" void kernel_launch(void* const* d_in, const int* in_sizes, int n_in,
                              void* d_out, int out_size)
{
    const float* x      = (const float*)d_in[0];
    const int*   ei     = (const int*)d_in[1];
    const int*   et     = (const int*)d_in[2];
    const float* bases1 = (const float*)d_in[3];
    const float* comp1  = (const float*)d_in[4];
    const float* root1  = (const float*)d_in[5];
    const float* bias1  = (const float*)d_in[6];
    const float* bases2 = (const float*)d_in[7];
    const float* comp2  = (const float*)d_in[8];
    const float* root2  = (const float*)d_in[9];
    const float* bias2  = (const float*)d_in[10];
    const int*   src    = ei;
    const int*   dst    = ei + EE;

    void *p;
    float *Y, *z, *xr, *W1, *W2, *inv, *esc;
    int *cnt, *hist, *off, *es, *ed, *ets;
    cudaGetSymbolAddress(&p, g_Y);    Y    = (float*)p;
    cudaGetSymbolAddress(&p, g_z);    z    = (float*)p;
    cudaGetSymbolAddress(&p, g_xr);   xr   = (float*)p;
    cudaGetSymbolAddress(&p, g_W1);   W1   = (float*)p;
    cudaGetSymbolAddress(&p, g_W2);   W2   = (float*)p;
    cudaGetSymbolAddress(&p, g_inv);  inv  = (float*)p;
    cudaGetSymbolAddress(&p, g_cnt);  cnt  = (int*)p;
    cudaGetSymbolAddress(&p, g_hist); hist = (int*)p;
    cudaGetSymbolAddress(&p, g_off);  off  = (int*)p;
    cudaGetSymbolAddress(&p, g_es);   es   = (int*)p;
    cudaGetSymbolAddress(&p, g_ed);   ed   = (int*)p;
    cudaGetSymbolAddress(&p, g_et);   ets  = (int*)p;
    cudaGetSymbolAddress(&p, g_esc);  esc  = (float*)p;

    cudaFuncSetAttribute(gemm2_kernel,
                         cudaFuncAttributeMaxDynamicSharedMemorySize, SMEM_BYTES);

    // weights + rounded x
    build_w_kernel<<<(KD * NW1 + 255) / 256, 256>>>(bases1, comp1, root1, W1, HIDD);
    build_w_kernel<<<(KD * NW2 + 255) / 256, 256>>>(bases2, comp2, root2, W2, ZDIM);
    round_x_kernel<<<(NN * KD / 4 + 255) / 256, 256>>>(x, xr);

    // topology: counts, inv, src-sorted edge permutation
    zero_topo_kernel<<<(NSEG + 255) / 256, 256>>>(cnt, hist);
    count_kernel<<<(EE + 255) / 256, 256>>>(src, dst, et, cnt, hist);
    inv_kernel<<<(NSEG + 255) / 256, 256>>>(cnt, inv);
    scan_kernel<<<1, 1024>>>(hist, off);
    permute_kernel<<<(EE + 255) / 256, 256>>>(src, dst, et, inv, off, es, ed, ets, esc);

    const int scatBlocks = (EE * 32 + 255) / 256;

    // ---- Layer 1 ----
    {
        dim3 g((NN + 127) / 128, NW1 / 128);
        gemm2_kernel<<<g, 256, SMEM_BYTES>>>(xr, W1, Y, z, bias1, NN, NW1, NR1, HIDD);
    }
    scatter_kernel<HIDD><<<scatBlocks, 256>>>(Y, es, ed, ets, esc, z);
    leaky_kernel<<<(NN * HIDD / 4 + 255) / 256, 256>>>(z);

    // ---- Layer 2 ----
    {
        dim3 g((NN + 127) / 128, NW2 / 128);
        gemm2_kernel<<<g, 256, SMEM_BYTES>>>(z, W2, Y, (float*)d_out, bias2, NN, NW2, NR2, ZDIM);
    }
    scatter_kernel<ZDIM><<<scatBlocks, 256>>>(Y, es, ed, ets, esc, (float*)d_out);
}

// round 7
// speedup vs baseline: 3.2181x; 1.0567x over previous
#include <cuda_runtime.h>
#include <cstdint>

#define NN    30000
#define RR    8
#define KD    256
#define HIDD  256
#define ZDIM  128
#define NBASE 30
#define NSEG  (NN*RR)
#define EE    480000
#define NW1   (RR*HIDD + HIDD)   // 2304
#define NW2   (RR*ZDIM + ZDIM)   // 1152
#define NR1   (RR*HIDD)          // 2048
#define NR2   (RR*ZDIM)          // 1024

// ---- static scratch ----
__device__ float g_Y[(size_t)NN * NR1];
__device__ float g_z[(size_t)NN * HIDD];
__device__ float g_xr[(size_t)NN * KD];
__device__ float g_W1[KD * NW1];
__device__ float g_W2[KD * NW2];
__device__ float g_inv[NSEG];
__device__ int   g_cnt[NSEG];
__device__ int   g_hist[NN];
__device__ int   g_offA[NN + 1];   // CSR row starts by dst (preserved)
__device__ int   g_offB[NN];       // cursor copy (mutated by permute)
__device__ int   g_epk[EE];        // (src<<3)|rel
__device__ float g_esc[EE];        // 1/cnt(dst,rel)

__device__ __forceinline__ unsigned f2tf32(float f)
{
    unsigned u;
    asm("cvt.rna.tf32.f32 %0, %1;" : "=r"(u) : "f"(f));
    return u;
}
__device__ __forceinline__ float rtf32(float f) { return __uint_as_float(f2tf32(f)); }

// ---------------------------------------------------------------------------
__global__ void build_w_kernel(const float* __restrict__ bases,
                               const float* __restrict__ comp,
                               const float* __restrict__ root,
                               float* __restrict__ W, int out)
{
    int idx = blockIdx.x * blockDim.x + threadIdx.x;
    int ncol = (RR + 1) * out;
    int total = KD * ncol;
    if (idx >= total) return;
    int i = idx / ncol;
    int col = idx - i * ncol;
    int r = col / out;
    int o = col - r * out;
    float s;
    if (r < RR) {
        s = 0.f;
#pragma unroll
        for (int b = 0; b < NBASE; b++)
            s += comp[r * NBASE + b] * bases[((size_t)b * KD + i) * out + o];
    } else {
        s = root[(size_t)i * out + o];
    }
    W[idx] = rtf32(s);
}

__global__ void round_x_kernel(const float* __restrict__ x, float* __restrict__ xr)
{
    int idx = blockIdx.x * blockDim.x + threadIdx.x;
    if (idx >= NN * KD / 4) return;
    float4 v = ((const float4*)x)[idx];
    v.x = rtf32(v.x); v.y = rtf32(v.y); v.z = rtf32(v.z); v.w = rtf32(v.w);
    ((float4*)xr)[idx] = v;
}

// ---------------------------------------------------------------------------
// Topology prep
// ---------------------------------------------------------------------------
__global__ void zero_topo_kernel(int* __restrict__ cnt, int* __restrict__ hist)
{
    int i = blockIdx.x * blockDim.x + threadIdx.x;
    if (i < NSEG) cnt[i] = 0;
    if (i < NN) hist[i] = 0;
}

__global__ void count_kernel(const int* __restrict__ dst,
                             const int* __restrict__ et,
                             int* __restrict__ cnt, int* __restrict__ hist)
{
    int e = blockIdx.x * blockDim.x + threadIdx.x;
    if (e >= EE) return;
    int d = dst[e];
    atomicAdd(&cnt[d * RR + et[e]], 1);
    atomicAdd(&hist[d], 1);
}

__global__ void inv_kernel(const int* __restrict__ cnt, float* __restrict__ inv)
{
    int i = blockIdx.x * blockDim.x + threadIdx.x;
    if (i < NSEG) inv[i] = 1.0f / (float)max(cnt[i], 1);
}

// Single-block exclusive scan: hist[NN] -> offA[NN+1] (starts) and offB (cursor)
__global__ void __launch_bounds__(1024) scan_kernel(const int* __restrict__ hist,
                                                    int* __restrict__ offA,
                                                    int* __restrict__ offB)
{
    __shared__ int part[1024];
    int tid = threadIdx.x;
    int base = tid * 32;
    int s = 0;
#pragma unroll
    for (int j = 0; j < 32; j++) {
        int idx = base + j;
        if (idx < NN) s += hist[idx];
    }
    part[tid] = s;
    __syncthreads();
    for (int d = 1; d < 1024; d <<= 1) {
        int v = 0;
        if (tid >= d) v = part[tid - d];
        __syncthreads();
        if (tid >= d) part[tid] += v;
        __syncthreads();
    }
    int run = (tid > 0) ? part[tid - 1] : 0;
#pragma unroll
    for (int j = 0; j < 32; j++) {
        int idx = base + j;
        if (idx < NN) { offA[idx] = run; offB[idx] = run; run += hist[idx]; }
    }
    if (tid == 1023) offA[NN] = part[1023];
}

__global__ void permute_kernel(const int* __restrict__ src,
                               const int* __restrict__ dst,
                               const int* __restrict__ et,
                               const float* __restrict__ inv,
                               int* __restrict__ offB,
                               int* __restrict__ epk, float* __restrict__ esc)
{
    int e = blockIdx.x * blockDim.x + threadIdx.x;
    if (e >= EE) return;
    int s = src[e], d = dst[e], t = et[e];
    int pos = atomicAdd(&offB[d], 1);
    epk[pos] = (s << 3) | t;
    esc[pos] = inv[d * RR + t];
}

// ---------------------------------------------------------------------------
// tf32 GEMM, cp.async double-buffered, split epilogue (relation cols -> Yr,
// root cols -> dest with bias).
// ---------------------------------------------------------------------------
#define AS_STRIDE 36
#define BS_STRIDE 136
#define AS_WORDS  (128*AS_STRIDE)
#define BS_WORDS  (32*BS_STRIDE)
#define SMEM_BYTES ((2*AS_WORDS + 2*BS_WORDS)*4)

__device__ __forceinline__ void cp16(uint32_t saddr, const void* g, bool pred)
{
    int sz = pred ? 16 : 0;
    asm volatile("cp.async.cg.shared.global [%0], [%1], 16, %2;"
                 :: "r"(saddr), "l"(g), "r"(sz));
}

__device__ __forceinline__ void mma_tf32(float c[4], const unsigned a[4], const unsigned b[2])
{
    asm volatile("mma.sync.aligned.m16n8k8.row.col.f32.tf32.tf32.f32 "
                 "{%0,%1,%2,%3}, {%4,%5,%6,%7}, {%8,%9}, {%0,%1,%2,%3};"
                 : "+f"(c[0]), "+f"(c[1]), "+f"(c[2]), "+f"(c[3])
                 : "r"(a[0]), "r"(a[1]), "r"(a[2]), "r"(a[3]),
                   "r"(b[0]), "r"(b[1]));
}

__global__ void __launch_bounds__(256)
gemm2_kernel(const float* __restrict__ A, const float* __restrict__ W,
             float* __restrict__ Yr, float* __restrict__ dest,
             const float* __restrict__ bias,
             int M, int Ntot, int NR, int OUT)
{
    extern __shared__ float sm[];
    const uint32_t smb = (uint32_t)__cvta_generic_to_shared(sm);

    const int tid   = threadIdx.x;
    const int lane  = tid & 31;
    const int warp  = tid >> 5;
    const int warpM = warp >> 1;
    const int warpN = warp & 1;
    const int gid   = lane >> 2;
    const int tig   = lane & 3;
    const int bm    = blockIdx.x * 128;
    const int bn    = blockIdx.y * 128;

    float acc[2][8][4];
#pragma unroll
    for (int mt = 0; mt < 2; mt++)
#pragma unroll
        for (int nt = 0; nt < 8; nt++)
#pragma unroll
            for (int q = 0; q < 4; q++) acc[mt][nt][q] = 0.f;

    auto loadA = [&](int stage, int k0) {
        uint32_t base = smb + (uint32_t)(stage * AS_WORDS) * 4;
#pragma unroll
        for (int i = 0; i < 4; i++) {
            int c = tid + 256 * i;
            int row = c >> 3, kc = c & 7;
            int gm = bm + row;
            const float* g = A + (size_t)gm * KD + k0 + kc * 4;
            cp16(base + (uint32_t)(row * AS_STRIDE + kc * 4) * 4, g, gm < M);
        }
    };
    auto loadB = [&](int stage, int k0) {
        uint32_t base = smb + (uint32_t)(2 * AS_WORDS + stage * BS_WORDS) * 4;
#pragma unroll
        for (int i = 0; i < 4; i++) {
            int c = tid + 256 * i;
            int kr = c >> 5, nc = c & 31;
            const float* g = W + (size_t)(k0 + kr) * Ntot + bn + nc * 4;
            cp16(base + (uint32_t)(kr * BS_STRIDE + nc * 4) * 4, g, true);
        }
    };

    loadA(0, 0); loadB(0, 0);
    asm volatile("cp.async.commit_group;");

    const int KT = KD / 32;
    for (int kt = 0; kt < KT; kt++) {
        int cur = kt & 1;
        if (kt + 1 < KT) {
            loadA(cur ^ 1, (kt + 1) * 32);
            loadB(cur ^ 1, (kt + 1) * 32);
            asm volatile("cp.async.commit_group;");
            asm volatile("cp.async.wait_group 1;");
        } else {
            asm volatile("cp.async.wait_group 0;");
        }
        __syncthreads();

        const unsigned* Au = (const unsigned*)(sm + cur * AS_WORDS);
        const unsigned* Bu = (const unsigned*)(sm + 2 * AS_WORDS + cur * BS_WORDS);

#pragma unroll
        for (int ks = 0; ks < 4; ks++) {
            const int kb = ks * 8;
            unsigned af[2][4];
#pragma unroll
            for (int mt = 0; mt < 2; mt++) {
                int mrow = warpM * 32 + mt * 16;
                af[mt][0] = Au[(mrow + gid) * AS_STRIDE + kb + tig];
                af[mt][1] = Au[(mrow + gid + 8) * AS_STRIDE + kb + tig];
                af[mt][2] = Au[(mrow + gid) * AS_STRIDE + kb + tig + 4];
                af[mt][3] = Au[(mrow + gid + 8) * AS_STRIDE + kb + tig + 4];
            }
#pragma unroll
            for (int nt = 0; nt < 8; nt++) {
                int ncol = warpN * 64 + nt * 8;
                unsigned bf[2];
                bf[0] = Bu[(kb + tig) * BS_STRIDE + ncol + gid];
                bf[1] = Bu[(kb + tig + 4) * BS_STRIDE + ncol + gid];
                mma_tf32(acc[0][nt], af[0], bf);
                mma_tf32(acc[1][nt], af[1], bf);
            }
        }
        __syncthreads();
    }

#pragma unroll
    for (int mt = 0; mt < 2; mt++) {
#pragma unroll
        for (int nt = 0; nt < 8; nt++) {
            int r0 = bm + warpM * 32 + mt * 16 + gid;
            int r1 = r0 + 8;
            int c  = bn + warpN * 64 + nt * 8 + tig * 2;
            if (c < NR) {
                if (r0 < M) *(float2*)(Yr + (size_t)r0 * NR + c) =
                    make_float2(acc[mt][nt][0], acc[mt][nt][1]);
                if (r1 < M) *(float2*)(Yr + (size_t)r1 * NR + c) =
                    make_float2(acc[mt][nt][2], acc[mt][nt][3]);
            } else {
                int cc = c - NR;
                float bx = bias[cc], by = bias[cc + 1];
                if (r0 < M) *(float2*)(dest + (size_t)r0 * OUT + cc) =
                    make_float2(acc[mt][nt][0] + bx, acc[mt][nt][1] + by);
                if (r1 < M) *(float2*)(dest + (size_t)r1 * OUT + cc) =
                    make_float2(acc[mt][nt][2] + bx, acc[mt][nt][3] + by);
            }
        }
    }
}

// ---------------------------------------------------------------------------
// dst-owned scatter: warp w owns node w. Accumulate incoming edges in regs,
// single plain RMW of the output row. LEAKY folds activation + tf32 re-round.
// ---------------------------------------------------------------------------
template<int OUT, bool LEAKY>
__global__ void __launch_bounds__(256)
scatter_dst_kernel(const float* __restrict__ Yr,
                   const int* __restrict__ epk,
                   const float* __restrict__ esc,
                   const int* __restrict__ offA,
                   float* __restrict__ out)
{
    const int NR = RR * OUT;
    const int IT = OUT / 128;
    int w = (blockIdx.x * blockDim.x + threadIdx.x) >> 5;
    if (w >= NN) return;
    int lane = threadIdx.x & 31;
    int beg = offA[w], end = offA[w + 1];

    float4 acc[IT];
#pragma unroll
    for (int it = 0; it < IT; it++) acc[it] = make_float4(0.f, 0.f, 0.f, 0.f);

    for (int e = beg; e < end; e++) {
        int pk = epk[e];
        float sc = esc[e];
        const float4* yr = (const float4*)(Yr + (size_t)(pk >> 3) * NR + (pk & 7) * OUT);
#pragma unroll
        for (int it = 0; it < IT; it++) {
            float4 v = yr[lane + it * 32];
            acc[it].x += sc * v.x; acc[it].y += sc * v.y;
            acc[it].z += sc * v.z; acc[it].w += sc * v.w;
        }
    }

    float4* o4 = (float4*)(out + (size_t)w * OUT);
#pragma unroll
    for (int it = 0; it < IT; it++) {
        float4 v = o4[lane + it * 32];
        v.x += acc[it].x; v.y += acc[it].y; v.z += acc[it].z; v.w += acc[it].w;
        if (LEAKY) {
            v.x = rtf32(v.x > 0.f ? v.x : 0.01f * v.x);
            v.y = rtf32(v.y > 0.f ? v.y : 0.01f * v.y);
            v.z = rtf32(v.z > 0.f ? v.z : 0.01f * v.z);
            v.w = rtf32(v.w > 0.f ? v.w : 0.01f * v.w);
        }
        o4[lane + it * 32] = v;
    }
}

// ---------------------------------------------------------------------------
extern "C" void kernel_launch(void* const* d_in, const int* in_sizes, int n_in,
                              void* d_out, int out_size)
{
    const float* x      = (const float*)d_in[0];
    const int*   ei     = (const int*)d_in[1];
    const int*   et     = (const int*)d_in[2];
    const float* bases1 = (const float*)d_in[3];
    const float* comp1  = (const float*)d_in[4];
    const float* root1  = (const float*)d_in[5];
    const float* bias1  = (const float*)d_in[6];
    const float* bases2 = (const float*)d_in[7];
    const float* comp2  = (const float*)d_in[8];
    const float* root2  = (const float*)d_in[9];
    const float* bias2  = (const float*)d_in[10];
    const int*   src    = ei;
    const int*   dst    = ei + EE;

    void *p;
    float *Y, *z, *xr, *W1, *W2, *inv, *esc;
    int *cnt, *hist, *offA, *offB, *epk;
    cudaGetSymbolAddress(&p, g_Y);    Y    = (float*)p;
    cudaGetSymbolAddress(&p, g_z);    z    = (float*)p;
    cudaGetSymbolAddress(&p, g_xr);   xr   = (float*)p;
    cudaGetSymbolAddress(&p, g_W1);   W1   = (float*)p;
    cudaGetSymbolAddress(&p, g_W2);   W2   = (float*)p;
    cudaGetSymbolAddress(&p, g_inv);  inv  = (float*)p;
    cudaGetSymbolAddress(&p, g_cnt);  cnt  = (int*)p;
    cudaGetSymbolAddress(&p, g_hist); hist = (int*)p;
    cudaGetSymbolAddress(&p, g_offA); offA = (int*)p;
    cudaGetSymbolAddress(&p, g_offB); offB = (int*)p;
    cudaGetSymbolAddress(&p, g_epk);  epk  = (int*)p;
    cudaGetSymbolAddress(&p, g_esc);  esc  = (float*)p;

    cudaFuncSetAttribute(gemm2_kernel,
                         cudaFuncAttributeMaxDynamicSharedMemorySize, SMEM_BYTES);

    build_w_kernel<<<(KD * NW1 + 255) / 256, 256>>>(bases1, comp1, root1, W1, HIDD);
    build_w_kernel<<<(KD * NW2 + 255) / 256, 256>>>(bases2, comp2, root2, W2, ZDIM);
    round_x_kernel<<<(NN * KD / 4 + 255) / 256, 256>>>(x, xr);

    zero_topo_kernel<<<(NSEG + 255) / 256, 256>>>(cnt, hist);
    count_kernel<<<(EE + 255) / 256, 256>>>(dst, et, cnt, hist);
    inv_kernel<<<(NSEG + 255) / 256, 256>>>(cnt, inv);
    scan_kernel<<<1, 1024>>>(hist, offA, offB);
    permute_kernel<<<(EE + 255) / 256, 256>>>(src, dst, et, inv, offB, epk, esc);

    const int scatBlocks = (NN * 32 + 255) / 256;

    // ---- Layer 1 ----
    {
        dim3 g((NN + 127) / 128, NW1 / 128);
        gemm2_kernel<<<g, 256, SMEM_BYTES>>>(xr, W1, Y, z, bias1, NN, NW1, NR1, HIDD);
    }
    scatter_dst_kernel<HIDD, true><<<scatBlocks, 256>>>(Y, epk, esc, offA, z);

    // ---- Layer 2 ----
    {
        dim3 g((NN + 127) / 128, NW2 / 128);
        gemm2_kernel<<<g, 256, SMEM_BYTES>>>(z, W2, Y, (float*)d_out, bias2, NN, NW2, NR2, ZDIM);
    }
    scatter_dst_kernel<ZDIM, false><<<scatBlocks, 256>>>(Y, epk, esc, offA, (float*)d_out);
}